// round 11
// baseline (speedup 1.0000x reference)
#include <cuda_runtime.h>
#include <cuda_fp16.h>
#include <cstdint>

// PS-ROI Align, two-phase. R10 inner loop (fp16 SMEM slice + HFMA2 rowsums,
// fp32 y-combine, table prefetch) with occupancy raised 4 -> 6 CTAs/SM
// (fp16 slice is only 25.6KB) and the single-wave grid rescaled to 49 x 18.

namespace {
constexpr int POOLN       = 7;
constexpr int TOTAL_BINS  = 49;
constexpr int ALPHA       = 32;
constexpr int HH          = 20;
constexpr int WW          = 20;
constexpr int THREADS     = 256;
constexpr int GROUPS      = THREADS / 8;        // 32 rois per iter
constexpr int CHUNKS      = 18;                 // 49*18 = 882 blocks = 1 wave @ occ6
constexpr int MAX_ROIS    = 8192;
constexpr int SMEM_F4     = HH * WW * (ALPHA / 4);  // 3200 8B fp16 chunks
constexpr int SMEM_BYTES  = SMEM_F4 * 8;            // 25600 B
}

// .x = bitcast int: i0 | i1<<8 | i2<<16 (clamped indices); .y/.z/.w = W0,W1,W2
// Weights pre-scaled by 0.5 per axis (product = the 0.25 mean factor).
__device__ float4 g_TX[MAX_ROIS * POOLN];
__device__ float4 g_TY[MAX_ROIS * POOLN];

__device__ __forceinline__ float4 axis_record(float origin, float step, int pos)
{
    const float sc = 19.0f / 20.0f;
    float c1 = (origin + (float)pos * step) * sc;
    float c2 = (origin + (float)(pos + 1) * step) * sc;

    float f1 = floorf(c1), f2 = floorf(c2);
    float w1 = c1 - f1,    w2 = c2 - f2;
    float v1 = (c1 >= 0.0f && c1 <= 19.0f) ? 1.0f : 0.0f;
    float v2 = (c2 >= 0.0f && c2 <= 19.0f) ? 1.0f : 0.0f;

    int a1 = min(max((int)f1, 0), 19);
    int b1 = min(a1 + 1, 19);
    int a2 = min(max((int)f2, 0), 19);
    int b2 = min(a2 + 1, 19);

    int o1 = b1 - a1;
    int o2 = min(max(a2 - a1, 0), 2);
    int o3 = min(max(b2 - a1, 0), 2);

    float u1 = v1 - v1 * w1;
    float u2 = v1 * w1;
    float u3 = v2 - v2 * w2;
    float u4 = v2 * w2;

    float W0 = u1 + (o1 == 0 ? u2 : 0.0f) + (o2 == 0 ? u3 : 0.0f) + (o3 == 0 ? u4 : 0.0f);
    float W1 =      (o1 == 1 ? u2 : 0.0f) + (o2 == 1 ? u3 : 0.0f) + (o3 == 1 ? u4 : 0.0f);
    float W2 =                              (o2 == 2 ? u3 : 0.0f) + (o3 == 2 ? u4 : 0.0f);

    int i0 = a1;
    int i1 = min(a1 + 1, 19);
    int i2 = min(a1 + 2, 19);

    float4 rec;
    rec.x = __int_as_float(i0 | (i1 << 8) | (i2 << 16));
    rec.y = 0.5f * W0; rec.z = 0.5f * W1; rec.w = 0.5f * W2;
    return rec;
}

__global__ void psroi_setup_kernel(const float4* __restrict__ rois4, int R)
{
    int idx = blockIdx.x * blockDim.x + threadIdx.x;   // roi*7 + pos
    if (idx >= R * POOLN) return;
    int roi = idx / POOLN;
    int pos = idx - roi * POOLN;
    float4 r = __ldg(&rois4[roi]);
    g_TX[idx] = axis_record(r.x, r.z * (1.0f / 7.0f), pos);
    g_TY[idx] = axis_record(r.y, r.w * (1.0f / 7.0f), pos);
}

// ---- packed f32x2 helpers ----
__device__ __forceinline__ unsigned long long pack2(float a) {
    unsigned long long r;
    asm("mov.b64 %0, {%1, %1};" : "=l"(r) : "f"(a));
    return r;
}
__device__ __forceinline__ unsigned long long packf2(float lo, float hi) {
    unsigned long long r;
    asm("mov.b64 %0, {%1, %2};" : "=l"(r) : "f"(lo), "f"(hi));
    return r;
}
__device__ __forceinline__ unsigned long long mul2(unsigned long long a,
                                                   unsigned long long b) {
    unsigned long long r;
    asm("mul.rn.f32x2 %0, %1, %2;" : "=l"(r) : "l"(a), "l"(b));
    return r;
}
__device__ __forceinline__ void fma2(unsigned long long& d,
                                     unsigned long long a,
                                     unsigned long long b) {
    asm("fma.rn.f32x2 %0, %1, %2, %0;" : "+l"(d) : "l"(a), "l"(b));
}
// 8B fp16 tap load: 4 alphas as 2 x half2, no conversion.
__device__ __forceinline__ void lds_h2x2(__half2& h0, __half2& h1,
                                         uint32_t addr) {
    uint32_t lo, hi;
    asm("ld.shared.v2.b32 {%0, %1}, [%2];" : "=r"(lo), "=r"(hi) : "r"(addr));
    h0 = *reinterpret_cast<__half2*>(&lo);
    h1 = *reinterpret_cast<__half2*>(&hi);
}
__device__ __forceinline__ unsigned long long h2_to_f2(__half2 h) {
    float2 f = __half22float2(h);
    return packf2(f.x, f.y);
}

__global__ __launch_bounds__(THREADS, 6)
void psroi_main_kernel(const float4* __restrict__ img4,
                       ulonglong2* __restrict__ out2,
                       int R)
{
    extern __shared__ uint32_t sh[];   // fp16 slice: [pix = y*20+x][alpha 0..31]

    const int bin = blockIdx.x;        // 0..48
    const int bx  = bin / POOLN;
    const int by  = bin % POOLN;

    const uint32_t smem0 = (uint32_t)__cvta_generic_to_shared(sh);

    {   // stage this bin's slice, converting fp32 -> fp16 (25.6KB)
        const int binoff4 = bin * (ALPHA / 4);
        #pragma unroll 4
        for (int p = threadIdx.x; p < SMEM_F4; p += THREADS) {
            int pix = p >> 3;
            int aq  = p & 7;
            float4 v = img4[pix * (TOTAL_BINS * ALPHA / 4) + binoff4 + aq];
            __half2 h0 = __float22half2_rn(make_float2(v.x, v.y));
            __half2 h1 = __float22half2_rn(make_float2(v.z, v.w));
            uint32_t u0 = *reinterpret_cast<uint32_t*>(&h0);
            uint32_t u1 = *reinterpret_cast<uint32_t*>(&h1);
            asm volatile("st.shared.v2.b32 [%0], {%1, %2};"
                         :: "r"(smem0 + (uint32_t)p * 8u), "r"(u0), "r"(u1));
        }
    }
    __syncthreads();

    const int grp = threadIdx.x >> 3;
    const int q   = threadIdx.x & 7;

    const int per_chunk = (R + CHUNKS - 1) / CHUNKS;     // 456
    const int roi_begin = blockIdx.y * per_chunk;
    const int roi_end   = min(roi_begin + per_chunk, R);
    const int iters     = (roi_end - roi_begin + GROUPS - 1) / GROUPS;

    // fp16 layout: pixel chunk = 64B, q offset = q*8B
    const uint32_t sbase = smem0 + (uint32_t)(q * 8);

    // prefetch first iteration's table records
    int roi_n = roi_begin + grp;
    int rc    = min(roi_n, roi_end - 1);
    float4 wxn = __ldg(&g_TX[rc * POOLN + bx]);
    float4 wyn = __ldg(&g_TY[rc * POOLN + by]);

    #pragma unroll 1
    for (int it = 0; it < iters; ++it) {
        const int roi = roi_n;
        const float4 wx = wxn;
        const float4 wy = wyn;

        roi_n += GROUPS;
        rc = min(roi_n, roi_end - 1);
        wxn = __ldg(&g_TX[rc * POOLN + bx]);
        wyn = __ldg(&g_TY[rc * POOLN + by]);

        const uint32_t px = (uint32_t)__float_as_int(wx.x);
        const uint32_t py = (uint32_t)__float_as_int(wy.x);
        // column byte offsets: x*64 ; row byte offsets: y*20*64 = y*1280
        const uint32_t c0 = sbase + ((px & 255u) << 6);
        const uint32_t c1 = sbase + (((px >> 8) & 255u) << 6);
        const uint32_t c2 = sbase + (((px >> 16) & 255u) << 6);
        const uint32_t r0 = (py & 255u) * 1280u;
        const uint32_t r1 = ((py >> 8) & 255u) * 1280u;
        const uint32_t r2 = ((py >> 16) & 255u) * 1280u;

        // x-weights in fp16 (one conversion per iter, not per tap)
        const __half2 wx0h = __float2half2_rn(wx.y);
        const __half2 wx1h = __float2half2_rn(wx.z);
        const __half2 wx2h = __float2half2_rn(wx.w);
        // y-weights stay exact fp32
        const unsigned long long wy0 = pack2(wy.y);
        const unsigned long long wy1 = pack2(wy.z);
        const unsigned long long wy2 = pack2(wy.w);

        // Row sums in fp16: u_r = wx0*v0 + wx1*v1 + wx2*v2 per half2.
        #define ROWSUM_H(UA, UB, RADDR) do {             \
            __half2 v0a_, v0b_, v1a_, v1b_, v2a_, v2b_;  \
            lds_h2x2(v0a_, v0b_, (RADDR) + c0);          \
            lds_h2x2(v1a_, v1b_, (RADDR) + c1);          \
            lds_h2x2(v2a_, v2b_, (RADDR) + c2);          \
            UA = __hmul2(wx0h, v0a_);                    \
            UB = __hmul2(wx0h, v0b_);                    \
            UA = __hfma2(wx1h, v1a_, UA);                \
            UB = __hfma2(wx1h, v1b_, UB);                \
            UA = __hfma2(wx2h, v2a_, UA);                \
            UB = __hfma2(wx2h, v2b_, UB);                \
        } while (0)

        __half2 u0a, u0b, u1a, u1b, u2a, u2b;
        ROWSUM_H(u0a, u0b, r0);
        ROWSUM_H(u1a, u1b, r1);
        ROWSUM_H(u2a, u2b, r2);
        #undef ROWSUM_H

        // Convert the 6 row-sums to fp32 and combine exactly with wy.
        unsigned long long a01 = mul2(wy0, h2_to_f2(u0a));
        unsigned long long a23 = mul2(wy0, h2_to_f2(u0b));
        fma2(a01, wy1, h2_to_f2(u1a));
        fma2(a23, wy1, h2_to_f2(u1b));
        fma2(a01, wy2, h2_to_f2(u2a));
        fma2(a23, wy2, h2_to_f2(u2b));

        if (roi < roi_end) {
            ulonglong2 o; o.x = a01; o.y = a23;
            out2[roi * (TOTAL_BINS * ALPHA / 4) + bin * (ALPHA / 4) + q] = o;
        }
    }
}

extern "C" void kernel_launch(void* const* d_in, const int* in_sizes, int n_in,
                              void* d_out, int out_size)
{
    const float* p0 = (const float*)d_in[0];
    const float* p1 = (const float*)d_in[1];
    const float* img  = p0;
    const float* rois = p1;
    int rois_elems = in_sizes[1];
    if (in_sizes[0] < in_sizes[1]) {
        img = p1; rois = p0; rois_elems = in_sizes[0];
    }
    const int R = rois_elems / 4;      // 8192

    {
        int total = R * POOLN;
        int blocks = (total + 255) / 256;
        psroi_setup_kernel<<<blocks, 256>>>((const float4*)rois, R);
    }

    cudaFuncSetAttribute(psroi_main_kernel,
                         cudaFuncAttributeMaxDynamicSharedMemorySize, SMEM_BYTES);
    dim3 grid(TOTAL_BINS, CHUNKS);     // 49 x 18 = 882 blocks: 1 wave @ occ 6
    psroi_main_kernel<<<grid, THREADS, SMEM_BYTES>>>(
        (const float4*)img, (ulonglong2*)d_out, R);
}

// round 12
// speedup vs baseline: 1.0867x; 1.0867x over previous
#include <cuda_runtime.h>
#include <cuda_fp16.h>
#include <cstdint>

// PS-ROI Align, SINGLE fused kernel. Each block (bin, roi-chunk):
//   1. computes factorized 3-tap axis records for its chunk into SMEM
//      (eliminates the separate setup kernel + global tables entirely),
//   2. stages the bin's feature slice as fp16 (25.6KB),
//   3. 8-lane groups produce one (roi,bin) each via HFMA2 rowsums + exact
//      fp32 y-combine (R10 inner loop).
// 6 CTAs/SM (36.6KB SMEM each), grid 49 x 24.

namespace {
constexpr int POOLN       = 7;
constexpr int TOTAL_BINS  = 49;
constexpr int ALPHA       = 32;
constexpr int HH          = 20;
constexpr int WW          = 20;
constexpr int THREADS     = 256;
constexpr int GROUPS      = THREADS / 8;        // 32 rois per iter
constexpr int CHUNKS      = 24;                 // grid 49x24, per_chunk=342
constexpr int TBL_PAD     = 344;                // padded record slots
constexpr int SMEM_F4     = HH * WW * (ALPHA / 4);  // 3200 8B fp16 chunks
constexpr int SLICE_BYTES = SMEM_F4 * 8;            // 25600
constexpr int TX_OFF      = SLICE_BYTES;            // 25600
constexpr int TY_OFF      = TX_OFF + TBL_PAD * 16;  // 31104
constexpr int SMEM_BYTES  = TY_OFF + TBL_PAD * 16;  // 36608
}

// record: .x = bitcast int i0|i1<<8|i2<<16 (clamped indices); .y/.z/.w =
// W0,W1,W2 pre-scaled by 0.5 (the two axes' products give the 0.25 mean).
__device__ __forceinline__ float4 axis_record(float origin, float step, int pos)
{
    const float sc = 19.0f / 20.0f;
    float c1 = (origin + (float)pos * step) * sc;
    float c2 = (origin + (float)(pos + 1) * step) * sc;

    float f1 = floorf(c1), f2 = floorf(c2);
    float w1 = c1 - f1,    w2 = c2 - f2;
    float v1 = (c1 >= 0.0f && c1 <= 19.0f) ? 1.0f : 0.0f;
    float v2 = (c2 >= 0.0f && c2 <= 19.0f) ? 1.0f : 0.0f;

    int a1 = min(max((int)f1, 0), 19);
    int b1 = min(a1 + 1, 19);
    int a2 = min(max((int)f2, 0), 19);
    int b2 = min(a2 + 1, 19);

    int o1 = b1 - a1;
    int o2 = min(max(a2 - a1, 0), 2);
    int o3 = min(max(b2 - a1, 0), 2);

    float u1 = v1 - v1 * w1;
    float u2 = v1 * w1;
    float u3 = v2 - v2 * w2;
    float u4 = v2 * w2;

    float W0 = u1 + (o1 == 0 ? u2 : 0.0f) + (o2 == 0 ? u3 : 0.0f) + (o3 == 0 ? u4 : 0.0f);
    float W1 =      (o1 == 1 ? u2 : 0.0f) + (o2 == 1 ? u3 : 0.0f) + (o3 == 1 ? u4 : 0.0f);
    float W2 =                              (o2 == 2 ? u3 : 0.0f) + (o3 == 2 ? u4 : 0.0f);

    int i0 = a1;
    int i1 = min(a1 + 1, 19);
    int i2 = min(a1 + 2, 19);

    float4 rec;
    rec.x = __int_as_float(i0 | (i1 << 8) | (i2 << 16));
    rec.y = 0.5f * W0; rec.z = 0.5f * W1; rec.w = 0.5f * W2;
    return rec;
}

// ---- packed helpers ----
__device__ __forceinline__ unsigned long long pack2(float a) {
    unsigned long long r;
    asm("mov.b64 %0, {%1, %1};" : "=l"(r) : "f"(a));
    return r;
}
__device__ __forceinline__ unsigned long long packf2(float lo, float hi) {
    unsigned long long r;
    asm("mov.b64 %0, {%1, %2};" : "=l"(r) : "f"(lo), "f"(hi));
    return r;
}
__device__ __forceinline__ unsigned long long mul2(unsigned long long a,
                                                   unsigned long long b) {
    unsigned long long r;
    asm("mul.rn.f32x2 %0, %1, %2;" : "=l"(r) : "l"(a), "l"(b));
    return r;
}
__device__ __forceinline__ void fma2(unsigned long long& d,
                                     unsigned long long a,
                                     unsigned long long b) {
    asm("fma.rn.f32x2 %0, %1, %2, %0;" : "+l"(d) : "l"(a), "l"(b));
}
__device__ __forceinline__ void lds_h2x2(__half2& h0, __half2& h1,
                                         uint32_t addr) {
    uint32_t lo, hi;
    asm("ld.shared.v2.b32 {%0, %1}, [%2];" : "=r"(lo), "=r"(hi) : "r"(addr));
    h0 = *reinterpret_cast<__half2*>(&lo);
    h1 = *reinterpret_cast<__half2*>(&hi);
}
__device__ __forceinline__ float4 lds_f4(uint32_t addr) {
    float4 v;
    asm("ld.shared.v4.f32 {%0, %1, %2, %3}, [%4];"
        : "=f"(v.x), "=f"(v.y), "=f"(v.z), "=f"(v.w) : "r"(addr));
    return v;
}
__device__ __forceinline__ void sts_f4(uint32_t addr, float4 v) {
    asm volatile("st.shared.v4.f32 [%0], {%1, %2, %3, %4};"
                 :: "r"(addr), "f"(v.x), "f"(v.y), "f"(v.z), "f"(v.w));
}
__device__ __forceinline__ unsigned long long h2_to_f2(__half2 h) {
    float2 f = __half22float2(h);
    return packf2(f.x, f.y);
}

__global__ __launch_bounds__(THREADS, 6)
void psroi_fused_kernel(const float4* __restrict__ img4,
                        const float4* __restrict__ rois4,
                        ulonglong2* __restrict__ out2,
                        int R)
{
    extern __shared__ uint32_t sh[];

    const int bin = blockIdx.x;        // 0..48
    const int bx  = bin / POOLN;
    const int by  = bin % POOLN;

    const uint32_t smem0 = (uint32_t)__cvta_generic_to_shared(sh);
    const uint32_t txb   = smem0 + TX_OFF;
    const uint32_t tyb   = smem0 + TY_OFF;

    const int per_chunk = (R + CHUNKS - 1) / CHUNKS;     // 342
    const int roi_begin = blockIdx.y * per_chunk;
    const int roi_end   = min(roi_begin + per_chunk, R);
    const int cnt       = roi_end - roi_begin;

    // ---- phase A: compute this chunk's axis records into SMEM ----
    for (int i = threadIdx.x; i < cnt; i += THREADS) {
        float4 r = __ldg(&rois4[roi_begin + i]);     // x, y, w, h
        sts_f4(txb + (uint32_t)i * 16u, axis_record(r.x, r.z * (1.0f / 7.0f), bx));
        sts_f4(tyb + (uint32_t)i * 16u, axis_record(r.y, r.w * (1.0f / 7.0f), by));
    }

    // ---- phase B: stage the bin's feature slice as fp16 ----
    {
        const int binoff4 = bin * (ALPHA / 4);
        #pragma unroll 4
        for (int p = threadIdx.x; p < SMEM_F4; p += THREADS) {
            int pix = p >> 3;
            int aq  = p & 7;
            float4 v = img4[pix * (TOTAL_BINS * ALPHA / 4) + binoff4 + aq];
            __half2 h0 = __float22half2_rn(make_float2(v.x, v.y));
            __half2 h1 = __float22half2_rn(make_float2(v.z, v.w));
            uint32_t u0 = *reinterpret_cast<uint32_t*>(&h0);
            uint32_t u1 = *reinterpret_cast<uint32_t*>(&h1);
            asm volatile("st.shared.v2.b32 [%0], {%1, %2};"
                         :: "r"(smem0 + (uint32_t)p * 8u), "r"(u0), "r"(u1));
        }
    }
    __syncthreads();

    // ---- phase C: main loop ----
    const int grp = threadIdx.x >> 3;
    const int q   = threadIdx.x & 7;
    const int iters = (cnt + GROUPS - 1) / GROUPS;

    const uint32_t sbase = smem0 + (uint32_t)(q * 8);

    // prefetch first iteration's records (SMEM broadcast loads)
    int i_n = grp;
    int ic  = min(i_n, cnt - 1);
    float4 wxn = lds_f4(txb + (uint32_t)ic * 16u);
    float4 wyn = lds_f4(tyb + (uint32_t)ic * 16u);

    #pragma unroll 1
    for (int it = 0; it < iters; ++it) {
        const int i   = i_n;
        const float4 wx = wxn;
        const float4 wy = wyn;

        i_n += GROUPS;
        ic = min(i_n, cnt - 1);
        wxn = lds_f4(txb + (uint32_t)ic * 16u);
        wyn = lds_f4(tyb + (uint32_t)ic * 16u);

        const uint32_t px = (uint32_t)__float_as_int(wx.x);
        const uint32_t py = (uint32_t)__float_as_int(wy.x);
        // column byte offsets: x*64 ; row byte offsets: y*20*64 = y*1280
        const uint32_t c0 = sbase + ((px & 255u) << 6);
        const uint32_t c1 = sbase + (((px >> 8) & 255u) << 6);
        const uint32_t c2 = sbase + (((px >> 16) & 255u) << 6);
        const uint32_t r0 = (py & 255u) * 1280u;
        const uint32_t r1 = ((py >> 8) & 255u) * 1280u;
        const uint32_t r2 = ((py >> 16) & 255u) * 1280u;

        // x-weights in fp16 (one conversion per iter)
        const __half2 wx0h = __float2half2_rn(wx.y);
        const __half2 wx1h = __float2half2_rn(wx.z);
        const __half2 wx2h = __float2half2_rn(wx.w);
        // y-weights exact fp32
        const unsigned long long wy0 = pack2(wy.y);
        const unsigned long long wy1 = pack2(wy.z);
        const unsigned long long wy2 = pack2(wy.w);

        #define ROWSUM_H(UA, UB, RADDR) do {             \
            __half2 v0a_, v0b_, v1a_, v1b_, v2a_, v2b_;  \
            lds_h2x2(v0a_, v0b_, (RADDR) + c0);          \
            lds_h2x2(v1a_, v1b_, (RADDR) + c1);          \
            lds_h2x2(v2a_, v2b_, (RADDR) + c2);          \
            UA = __hmul2(wx0h, v0a_);                    \
            UB = __hmul2(wx0h, v0b_);                    \
            UA = __hfma2(wx1h, v1a_, UA);                \
            UB = __hfma2(wx1h, v1b_, UB);                \
            UA = __hfma2(wx2h, v2a_, UA);                \
            UB = __hfma2(wx2h, v2b_, UB);                \
        } while (0)

        __half2 u0a, u0b, u1a, u1b, u2a, u2b;
        ROWSUM_H(u0a, u0b, r0);
        ROWSUM_H(u1a, u1b, r1);
        ROWSUM_H(u2a, u2b, r2);
        #undef ROWSUM_H

        unsigned long long a01 = mul2(wy0, h2_to_f2(u0a));
        unsigned long long a23 = mul2(wy0, h2_to_f2(u0b));
        fma2(a01, wy1, h2_to_f2(u1a));
        fma2(a23, wy1, h2_to_f2(u1b));
        fma2(a01, wy2, h2_to_f2(u2a));
        fma2(a23, wy2, h2_to_f2(u2b));

        if (i < cnt) {
            const int roi = roi_begin + i;
            ulonglong2 o; o.x = a01; o.y = a23;
            out2[roi * (TOTAL_BINS * ALPHA / 4) + bin * (ALPHA / 4) + q] = o;
        }
    }
}

extern "C" void kernel_launch(void* const* d_in, const int* in_sizes, int n_in,
                              void* d_out, int out_size)
{
    const float* p0 = (const float*)d_in[0];
    const float* p1 = (const float*)d_in[1];
    const float* img  = p0;
    const float* rois = p1;
    int rois_elems = in_sizes[1];
    if (in_sizes[0] < in_sizes[1]) {
        img = p1; rois = p0; rois_elems = in_sizes[0];
    }
    const int R = rois_elems / 4;      // 8192

    cudaFuncSetAttribute(psroi_fused_kernel,
                         cudaFuncAttributeMaxDynamicSharedMemorySize, SMEM_BYTES);
    dim3 grid(TOTAL_BINS, CHUNKS);     // 49 x 24 = 1176 blocks
    psroi_fused_kernel<<<grid, THREADS, SMEM_BYTES>>>(
        (const float4*)img, (const float4*)rois, (ulonglong2*)d_out, R);
}

// round 13
// speedup vs baseline: 1.0987x; 1.0111x over previous
#include <cuda_runtime.h>
#include <cuda_fp16.h>
#include <cstdint>

// PS-ROI Align, single fused kernel. R12 structure (in-SMEM axis records +
// fp16 feature slice + HFMA2 rowsums) with:
//   - CHUNKS 24 -> 20 (980 blocks = 1.10 waves at occ 6, tables still fit)
//   - y-combine in fp16 (HFMA2) too: only 2 F2F per lane-iter remain.

namespace {
constexpr int POOLN       = 7;
constexpr int TOTAL_BINS  = 49;
constexpr int ALPHA       = 32;
constexpr int HH          = 20;
constexpr int WW          = 20;
constexpr int THREADS     = 256;
constexpr int GROUPS      = THREADS / 8;        // 32 rois per iter
constexpr int CHUNKS      = 20;                 // grid 49x20, per_chunk=410
constexpr int TBL_PAD     = 412;                // padded record slots
constexpr int SMEM_F4     = HH * WW * (ALPHA / 4);  // 3200 8B fp16 chunks
constexpr int SLICE_BYTES = SMEM_F4 * 8;            // 25600
constexpr int TX_OFF      = SLICE_BYTES;            // 25600
constexpr int TY_OFF      = TX_OFF + TBL_PAD * 16;  // 32192
constexpr int SMEM_BYTES  = TY_OFF + TBL_PAD * 16;  // 38784 (<= 38912 @ occ6)
}

// record: .x = bitcast int i0|i1<<8|i2<<16 (clamped indices); .y/.z/.w =
// W0,W1,W2 pre-scaled by 0.5 (the two axes' products give the 0.25 mean).
__device__ __forceinline__ float4 axis_record(float origin, float step, int pos)
{
    const float sc = 19.0f / 20.0f;
    float c1 = (origin + (float)pos * step) * sc;
    float c2 = (origin + (float)(pos + 1) * step) * sc;

    float f1 = floorf(c1), f2 = floorf(c2);
    float w1 = c1 - f1,    w2 = c2 - f2;
    float v1 = (c1 >= 0.0f && c1 <= 19.0f) ? 1.0f : 0.0f;
    float v2 = (c2 >= 0.0f && c2 <= 19.0f) ? 1.0f : 0.0f;

    int a1 = min(max((int)f1, 0), 19);
    int b1 = min(a1 + 1, 19);
    int a2 = min(max((int)f2, 0), 19);
    int b2 = min(a2 + 1, 19);

    int o1 = b1 - a1;
    int o2 = min(max(a2 - a1, 0), 2);
    int o3 = min(max(b2 - a1, 0), 2);

    float u1 = v1 - v1 * w1;
    float u2 = v1 * w1;
    float u3 = v2 - v2 * w2;
    float u4 = v2 * w2;

    float W0 = u1 + (o1 == 0 ? u2 : 0.0f) + (o2 == 0 ? u3 : 0.0f) + (o3 == 0 ? u4 : 0.0f);
    float W1 =      (o1 == 1 ? u2 : 0.0f) + (o2 == 1 ? u3 : 0.0f) + (o3 == 1 ? u4 : 0.0f);
    float W2 =                              (o2 == 2 ? u3 : 0.0f) + (o3 == 2 ? u4 : 0.0f);

    int i0 = a1;
    int i1 = min(a1 + 1, 19);
    int i2 = min(a1 + 2, 19);

    float4 rec;
    rec.x = __int_as_float(i0 | (i1 << 8) | (i2 << 16));
    rec.y = 0.5f * W0; rec.z = 0.5f * W1; rec.w = 0.5f * W2;
    return rec;
}

// ---- helpers ----
__device__ __forceinline__ void lds_h2x2(__half2& h0, __half2& h1,
                                         uint32_t addr) {
    uint32_t lo, hi;
    asm("ld.shared.v2.b32 {%0, %1}, [%2];" : "=r"(lo), "=r"(hi) : "r"(addr));
    h0 = *reinterpret_cast<__half2*>(&lo);
    h1 = *reinterpret_cast<__half2*>(&hi);
}
__device__ __forceinline__ float4 lds_f4(uint32_t addr) {
    float4 v;
    asm("ld.shared.v4.f32 {%0, %1, %2, %3}, [%4];"
        : "=f"(v.x), "=f"(v.y), "=f"(v.z), "=f"(v.w) : "r"(addr));
    return v;
}
__device__ __forceinline__ void sts_f4(uint32_t addr, float4 v) {
    asm volatile("st.shared.v4.f32 [%0], {%1, %2, %3, %4};"
                 :: "r"(addr), "f"(v.x), "f"(v.y), "f"(v.z), "f"(v.w));
}

__global__ __launch_bounds__(THREADS, 6)
void psroi_fused_kernel(const float4* __restrict__ img4,
                        const float4* __restrict__ rois4,
                        float4* __restrict__ out4,
                        int R)
{
    extern __shared__ uint32_t sh[];

    const int bin = blockIdx.x;        // 0..48
    const int bx  = bin / POOLN;
    const int by  = bin % POOLN;

    const uint32_t smem0 = (uint32_t)__cvta_generic_to_shared(sh);
    const uint32_t txb   = smem0 + TX_OFF;
    const uint32_t tyb   = smem0 + TY_OFF;

    const int per_chunk = (R + CHUNKS - 1) / CHUNKS;     // 410
    const int roi_begin = blockIdx.y * per_chunk;
    const int roi_end   = min(roi_begin + per_chunk, R);
    const int cnt       = roi_end - roi_begin;

    // ---- phase A: compute this chunk's axis records into SMEM ----
    for (int i = threadIdx.x; i < cnt; i += THREADS) {
        float4 r = __ldg(&rois4[roi_begin + i]);     // x, y, w, h
        sts_f4(txb + (uint32_t)i * 16u, axis_record(r.x, r.z * (1.0f / 7.0f), bx));
        sts_f4(tyb + (uint32_t)i * 16u, axis_record(r.y, r.w * (1.0f / 7.0f), by));
    }

    // ---- phase B: stage the bin's feature slice as fp16 ----
    {
        const int binoff4 = bin * (ALPHA / 4);
        #pragma unroll 4
        for (int p = threadIdx.x; p < SMEM_F4; p += THREADS) {
            int pix = p >> 3;
            int aq  = p & 7;
            float4 v = img4[pix * (TOTAL_BINS * ALPHA / 4) + binoff4 + aq];
            __half2 h0 = __float22half2_rn(make_float2(v.x, v.y));
            __half2 h1 = __float22half2_rn(make_float2(v.z, v.w));
            uint32_t u0 = *reinterpret_cast<uint32_t*>(&h0);
            uint32_t u1 = *reinterpret_cast<uint32_t*>(&h1);
            asm volatile("st.shared.v2.b32 [%0], {%1, %2};"
                         :: "r"(smem0 + (uint32_t)p * 8u), "r"(u0), "r"(u1));
        }
    }
    __syncthreads();

    // ---- phase C: main loop ----
    const int grp = threadIdx.x >> 3;
    const int q   = threadIdx.x & 7;
    const int iters = (cnt + GROUPS - 1) / GROUPS;

    const uint32_t sbase = smem0 + (uint32_t)(q * 8);

    // prefetch first iteration's records (SMEM broadcast loads)
    int i_n = grp;
    int ic  = min(i_n, cnt - 1);
    float4 wxn = lds_f4(txb + (uint32_t)ic * 16u);
    float4 wyn = lds_f4(tyb + (uint32_t)ic * 16u);

    #pragma unroll 1
    for (int it = 0; it < iters; ++it) {
        const int i   = i_n;
        const float4 wx = wxn;
        const float4 wy = wyn;

        i_n += GROUPS;
        ic = min(i_n, cnt - 1);
        wxn = lds_f4(txb + (uint32_t)ic * 16u);
        wyn = lds_f4(tyb + (uint32_t)ic * 16u);

        const uint32_t px = (uint32_t)__float_as_int(wx.x);
        const uint32_t py = (uint32_t)__float_as_int(wy.x);
        // column byte offsets: x*64 ; row byte offsets: y*20*64 = y*1280
        const uint32_t c0 = sbase + ((px & 255u) << 6);
        const uint32_t c1 = sbase + (((px >> 8) & 255u) << 6);
        const uint32_t c2 = sbase + (((px >> 16) & 255u) << 6);
        const uint32_t r0 = (py & 255u) * 1280u;
        const uint32_t r1 = ((py >> 8) & 255u) * 1280u;
        const uint32_t r2 = ((py >> 16) & 255u) * 1280u;

        // all weights fp16 (one conversion per iter per weight)
        const __half2 wx0h = __float2half2_rn(wx.y);
        const __half2 wx1h = __float2half2_rn(wx.z);
        const __half2 wx2h = __float2half2_rn(wx.w);
        const __half2 wy0h = __float2half2_rn(wy.y);
        const __half2 wy1h = __float2half2_rn(wy.z);
        const __half2 wy2h = __float2half2_rn(wy.w);

        #define ROWSUM_H(UA, UB, RADDR) do {             \
            __half2 v0a_, v0b_, v1a_, v1b_, v2a_, v2b_;  \
            lds_h2x2(v0a_, v0b_, (RADDR) + c0);          \
            lds_h2x2(v1a_, v1b_, (RADDR) + c1);          \
            lds_h2x2(v2a_, v2b_, (RADDR) + c2);          \
            UA = __hmul2(wx0h, v0a_);                    \
            UB = __hmul2(wx0h, v0b_);                    \
            UA = __hfma2(wx1h, v1a_, UA);                \
            UB = __hfma2(wx1h, v1b_, UB);                \
            UA = __hfma2(wx2h, v2a_, UA);                \
            UB = __hfma2(wx2h, v2b_, UB);                \
        } while (0)

        __half2 u0a, u0b, u1a, u1b, u2a, u2b;
        ROWSUM_H(u0a, u0b, r0);
        ROWSUM_H(u1a, u1b, r1);
        ROWSUM_H(u2a, u2b, r2);
        #undef ROWSUM_H

        // y-combine in fp16 as well; only the final two conversions to fp32.
        __half2 b0 = __hmul2(wy0h, u0a);
        __half2 b1 = __hmul2(wy0h, u0b);
        b0 = __hfma2(wy1h, u1a, b0);
        b1 = __hfma2(wy1h, u1b, b1);
        b0 = __hfma2(wy2h, u2a, b0);
        b1 = __hfma2(wy2h, u2b, b1);

        if (i < cnt) {
            const int roi = roi_begin + i;
            float2 f0 = __half22float2(b0);
            float2 f1 = __half22float2(b1);
            float4 o = make_float4(f0.x, f0.y, f1.x, f1.y);
            out4[roi * (TOTAL_BINS * ALPHA / 4) + bin * (ALPHA / 4) + q] = o;
        }
    }
}

extern "C" void kernel_launch(void* const* d_in, const int* in_sizes, int n_in,
                              void* d_out, int out_size)
{
    const float* p0 = (const float*)d_in[0];
    const float* p1 = (const float*)d_in[1];
    const float* img  = p0;
    const float* rois = p1;
    int rois_elems = in_sizes[1];
    if (in_sizes[0] < in_sizes[1]) {
        img = p1; rois = p0; rois_elems = in_sizes[0];
    }
    const int R = rois_elems / 4;      // 8192

    cudaFuncSetAttribute(psroi_fused_kernel,
                         cudaFuncAttributeMaxDynamicSharedMemorySize, SMEM_BYTES);
    dim3 grid(TOTAL_BINS, CHUNKS);     // 49 x 20 = 980 blocks (1.10 waves @ occ6)
    psroi_fused_kernel<<<grid, THREADS, SMEM_BYTES>>>(
        (const float4*)img, (const float4*)rois, (float4*)d_out, R);
}